// round 1
// baseline (speedup 1.0000x reference)
#include <cuda_runtime.h>
#include <cuda_bf16.h>

// Problem constants (fixed by setup_inputs)
#define B_GRAPHS 2000
#define LGPG 100      // line-graph nodes per graph
#define NPG 20        // original nodes per graph
#define ELPG 10       // labeled edges per graph
#define D 300
#define HDIM 100      // D/3
#define TWOH 200      // 2*HDIM
#define N_LG (B_GRAPHS * LGPG)      // 200000
#define N_NODES (B_GRAPHS * NPG)    // 40000
#define E_LAB (B_GRAPHS * ELPG)     // 20000

// Output layout (flattened tuple, float32):
//  [0, 12,000,000)              x_new  [N_NODES, D]
//  [12,000,000, 12,040,000)     edge_index_labeled_new [2, E_LAB]
//  [12,040,000, 12,042,001)     ptr_new [B+1]
//  [12,042,001, 12,082,001)     batch_vec [N_NODES]
#define OFF_EDGE 12000000
#define OFF_PTR  12040000
#define OFF_BATCH 12042001
#define AUX_TOTAL 82001

// One CTA per graph. Accumulate incoming mean (cols 0..199) keyed by
// lg_node_idx[:,1] and outgoing mean (cols 200..299) keyed by lg_node_idx[:,0]
// into shared memory, then write the fused x_new tile.
__global__ __launch_bounds__(256) void graph_kernel(
    const float* __restrict__ x,          // [N_LG, D]
    const int* __restrict__ lg_node_idx,  // [N_LG, 2]
    float* __restrict__ out)              // [out_size]
{
    const int g = blockIdx.x;
    const int tid = threadIdx.x;

    __shared__ float acc_in[NPG][TWOH];   // 20*200*4 = 16000 B
    __shared__ float acc_out[NPG][HDIM];  // 20*100*4 =  8000 B
    __shared__ int cnt0[NPG];
    __shared__ int cnt1[NPG];
    __shared__ int sidx0[LGPG];
    __shared__ int sidx1[LGPG];

    // zero accumulators
    {
        float* a = &acc_in[0][0];
        for (int i = tid; i < NPG * TWOH; i += 256) a[i] = 0.0f;
        float* b = &acc_out[0][0];
        for (int i = tid; i < NPG * HDIM; i += 256) b[i] = 0.0f;
        if (tid < NPG) { cnt0[tid] = 0; cnt1[tid] = 0; }
    }
    __syncthreads();

    // load indices + counts
    if (tid < LGPG) {
        int i0 = lg_node_idx[(g * LGPG + tid) * 2 + 0];
        int i1 = lg_node_idx[(g * LGPG + tid) * 2 + 1];
        sidx0[tid] = i0;
        sidx1[tid] = i1;
        atomicAdd(&cnt0[i0], 1);
        atomicAdd(&cnt1[i1], 1);
    }
    __syncthreads();

    // accumulate: 100 rows * 300 floats = 7500 float4 per graph.
    // Row length 300 = 75 float4; split at col 200 = float4 index 50 (aligned),
    // so a float4 never straddles a row or the in/out column boundary.
    const float4* xv = reinterpret_cast<const float4*>(x) + (size_t)g * (LGPG * D / 4);
    for (int q = tid; q < LGPG * D / 4; q += 256) {
        int j  = q / 75;       // line-graph node within graph
        int dq = q - j * 75;   // float4 column
        float4 v = xv[q];
        if (dq < 50) {
            float* dst = &acc_in[sidx1[j]][dq * 4];
            atomicAdd(dst + 0, v.x);
            atomicAdd(dst + 1, v.y);
            atomicAdd(dst + 2, v.z);
            atomicAdd(dst + 3, v.w);
        } else {
            float* dst = &acc_out[sidx0[j]][dq * 4 - TWOH];
            atomicAdd(dst + 0, v.x);
            atomicAdd(dst + 1, v.y);
            atomicAdd(dst + 2, v.z);
            atomicAdd(dst + 3, v.w);
        }
    }
    __syncthreads();

    // write x_new tile: 20 rows * 300 floats = 1500 float4
    float4* ov = reinterpret_cast<float4*>(out) + (size_t)g * (NPG * D / 4);
    for (int q = tid; q < NPG * D / 4; q += 256) {
        int n  = q / 75;
        int dq = q - n * 75;
        float4 r;
        if (dq < 50) {
            int c = cnt1[n];
            float inv = (c > 0) ? (1.0f / (float)c) : 0.0f;
            const float* s = &acc_in[n][dq * 4];
            r.x = s[0] * inv; r.y = s[1] * inv; r.z = s[2] * inv; r.w = s[3] * inv;
        } else {
            int c = cnt0[n];
            float inv = (c > 0) ? (1.0f / (float)c) : 0.0f;
            const float* s = &acc_out[n][dq * 4 - TWOH];
            r.x = s[0] * inv; r.y = s[1] * inv; r.z = s[2] * inv; r.w = s[3] * inv;
        }
        ov[q] = r;
    }
}

// Aux outputs: edge_index_labeled_new, ptr_new, batch_vec (82,001 floats)
__global__ __launch_bounds__(256) void aux_kernel(
    const int* __restrict__ edge_index_labeled,  // [2, E_LAB]
    float* __restrict__ out)
{
    int i = blockIdx.x * blockDim.x + threadIdx.x;
    if (i >= AUX_TOTAL) return;
    if (i < 2 * E_LAB) {
        int e = i % E_LAB;
        int lg_pad = (e / ELPG) * LGPG;   // lg offset of the edge's graph
        out[OFF_EDGE + i] = (float)(edge_index_labeled[i] - lg_pad);
    } else if (i < 2 * E_LAB + (B_GRAPHS + 1)) {
        int k = i - 2 * E_LAB;
        out[OFF_PTR + k] = (float)(k * NPG);
    } else {
        int k = i - (2 * E_LAB + B_GRAPHS + 1);
        out[OFF_BATCH + k] = (float)(k / NPG);
    }
}

extern "C" void kernel_launch(void* const* d_in, const int* in_sizes, int n_in,
                              void* d_out, int out_size) {
    const float* x               = (const float*)d_in[0];
    const int*   lg_node_idx     = (const int*)d_in[1];
    // d_in[2]=ptr, d_in[3]=org_graph_size, d_in[4]=edge_label_size (constant, unused)
    const int*   edge_idx_lab    = (const int*)d_in[5];
    float* out = (float*)d_out;

    graph_kernel<<<B_GRAPHS, 256>>>(x, lg_node_idx, out);
    aux_kernel<<<(AUX_TOTAL + 255) / 256, 256>>>(edge_idx_lab, out);
}

// round 2
// speedup vs baseline: 1.7938x; 1.7938x over previous
#include <cuda_runtime.h>
#include <cuda_bf16.h>

// Problem constants (fixed by setup_inputs)
#define B_GRAPHS 2000
#define LGPG 100      // line-graph nodes per graph
#define NPG 20        // original nodes per graph
#define ELPG 10       // labeled edges per graph
#define D 300
#define HDIM 100
#define TWOH 200
#define N_LG (B_GRAPHS * LGPG)      // 200000
#define N_NODES (B_GRAPHS * NPG)    // 40000
#define E_LAB (B_GRAPHS * ELPG)     // 20000
#define ROWV 75                      // float4 per row (300/4)

// Output layout (flattened tuple, float32):
//  [0, 12,000,000)              x_new  [N_NODES, D]
//  [12,000,000, 12,040,000)     edge_index_labeled_new [2, E_LAB]
//  [12,040,000, 12,042,001)     ptr_new [B+1]
//  [12,042,001, 12,082,001)     batch_vec [N_NODES]
#define OFF_EDGE 12000000
#define OFF_PTR  12040000
#define OFF_BATCH 12042001

// One CTA per graph. Build per-node CSR contributor lists for both keys,
// then GATHER: each thread computes one float4 of x_new by summing the
// contributing rows' float4s directly from global. Each x element is read
// exactly once chip-wide; no data atomics at all.
__global__ __launch_bounds__(256) void graph_kernel(
    const float* __restrict__ x,                  // [N_LG, D]
    const int* __restrict__ lg_node_idx,          // [N_LG, 2]
    const int* __restrict__ edge_index_labeled,   // [2, E_LAB]
    float* __restrict__ out)
{
    const int g = blockIdx.x;
    const int tid = threadIdx.x;

    __shared__ int cur0[NPG], cur1[NPG];          // cursors (reused)
    __shared__ int off0[NPG + 1], off1[NPG + 1];  // CSR offsets
    __shared__ int list0[LGPG], list1[LGPG];      // rows per node
    __shared__ int idx0[LGPG], idx1[LGPG];
    __shared__ float inv0[NPG], inv1[NPG];

    if (tid < NPG) { cur0[tid] = 0; cur1[tid] = 0; }
    __syncthreads();

    if (tid < LGPG) {
        int i0 = lg_node_idx[(g * LGPG + tid) * 2 + 0];
        int i1 = lg_node_idx[(g * LGPG + tid) * 2 + 1];
        idx0[tid] = i0; idx1[tid] = i1;
        atomicAdd(&cur0[i0], 1);
        atomicAdd(&cur1[i1], 1);
    }
    __syncthreads();

    // tiny serial prefix sums (20 elements each)
    if (tid == 0) {
        int s = 0;
        for (int n = 0; n < NPG; n++) { off0[n] = s; s += cur0[n]; }
        off0[NPG] = s;
    } else if (tid == 32) {
        int s = 0;
        for (int n = 0; n < NPG; n++) { off1[n] = s; s += cur1[n]; }
        off1[NPG] = s;
    }
    __syncthreads();

    if (tid < NPG) {
        int c0 = off0[tid + 1] - off0[tid];
        int c1 = off1[tid + 1] - off1[tid];
        inv0[tid] = c0 > 0 ? 1.0f / (float)c0 : 0.0f;
        inv1[tid] = c1 > 0 ? 1.0f / (float)c1 : 0.0f;
        cur0[tid] = off0[tid];
        cur1[tid] = off1[tid];
    }
    __syncthreads();

    if (tid < LGPG) {
        int p0 = atomicAdd(&cur0[idx0[tid]], 1);
        list0[p0] = tid;
        int p1 = atomicAdd(&cur1[idx1[tid]], 1);
        list1[p1] = tid;
    }
    __syncthreads();

    // Gather phase: 20 nodes * 75 float4 = 1500 outputs per graph.
    const float4* xv = reinterpret_cast<const float4*>(x) + (size_t)g * (LGPG * ROWV);
    float4* ov = reinterpret_cast<float4*>(out) + (size_t)g * (NPG * ROWV);

    #pragma unroll 2
    for (int q = tid; q < NPG * ROWV; q += 256) {
        int n  = q / ROWV;
        int dq = q - n * ROWV;
        float sx = 0.f, sy = 0.f, sz = 0.f, sw = 0.f;
        float iv;
        if (dq < 50) {                   // incoming half: key = idx1
            int s = off1[n], e = off1[n + 1];
            iv = inv1[n];
            for (int k = s; k < e; k++) {
                float4 v = xv[list1[k] * ROWV + dq];
                sx += v.x; sy += v.y; sz += v.z; sw += v.w;
            }
        } else {                         // outgoing half: key = idx0
            int s = off0[n], e = off0[n + 1];
            iv = inv0[n];
            for (int k = s; k < e; k++) {
                float4 v = xv[list0[k] * ROWV + dq];
                sx += v.x; sy += v.y; sz += v.z; sw += v.w;
            }
        }
        float4 r; r.x = sx * iv; r.y = sy * iv; r.z = sz * iv; r.w = sw * iv;
        ov[q] = r;
    }

    // Aux outputs (fused, no second kernel)
    if (tid < 2 * ELPG) {
        int r = tid / ELPG, e = tid % ELPG;
        int gi = r * E_LAB + g * ELPG + e;
        out[OFF_EDGE + gi] = (float)(edge_index_labeled[gi] - g * LGPG);
    } else if (tid >= 64 && tid < 64 + NPG) {
        out[OFF_BATCH + g * NPG + (tid - 64)] = (float)g;
    } else if (tid == 96) {
        out[OFF_PTR + g] = (float)(g * NPG);
        if (g == B_GRAPHS - 1) out[OFF_PTR + B_GRAPHS] = (float)(B_GRAPHS * NPG);
    }
}

extern "C" void kernel_launch(void* const* d_in, const int* in_sizes, int n_in,
                              void* d_out, int out_size) {
    const float* x            = (const float*)d_in[0];
    const int*   lg_node_idx  = (const int*)d_in[1];
    // d_in[2]=ptr, d_in[3]=org_graph_size, d_in[4]=edge_label_size (constant, unused)
    const int*   edge_idx_lab = (const int*)d_in[5];
    float* out = (float*)d_out;

    graph_kernel<<<B_GRAPHS, 256>>>(x, lg_node_idx, edge_idx_lab, out);
}

// round 3
// speedup vs baseline: 2.1983x; 1.2255x over previous
#include <cuda_runtime.h>
#include <cuda_bf16.h>

// Problem constants (fixed by setup_inputs)
#define B_GRAPHS 2000
#define LGPG 100      // line-graph nodes per graph
#define NPG 20        // original nodes per graph
#define ELPG 10       // labeled edges per graph
#define D 300
#define ROWV 75       // float4 per row (300/4)
#define N_LG (B_GRAPHS * LGPG)
#define N_NODES (B_GRAPHS * NPG)
#define E_LAB (B_GRAPHS * ELPG)

// Output layout (flattened tuple, float32):
//  [0, 12,000,000)              x_new  [N_NODES, D]
//  [12,000,000, 12,040,000)     edge_index_labeled_new [2, E_LAB]
//  [12,040,000, 12,042,001)     ptr_new [B+1]
//  [12,042,001, 12,082,001)     batch_vec [N_NODES]
#define OFF_EDGE 12000000
#define OFF_PTR  12040000
#define OFF_BATCH 12042001

__device__ __forceinline__ float4 ldcs4(const float4* p) {
    float4 v;
    asm volatile("ld.global.cs.v4.f32 {%0,%1,%2,%3}, [%4];"
                 : "=f"(v.x), "=f"(v.y), "=f"(v.z), "=f"(v.w) : "l"(p));
    return v;
}
__device__ __forceinline__ void stcs4(float4* p, float4 v) {
    asm volatile("st.global.cs.v4.f32 [%0], {%1,%2,%3,%4};"
                 :: "l"(p), "f"(v.x), "f"(v.y), "f"(v.z), "f"(v.w) : "memory");
}

// One CTA per graph. Build per-node CSR contributor lists for both keys,
// then GATHER: warp w handles nodes w, w+8, ... For each node, lanes cover
// float4 columns in three uniform segments:
//   seg A: dq = lane        (0..31,  incoming list1)
//   seg B: dq = 32 + lane   (<50,    incoming list1)
//   seg C: dq = 50 + lane   (<75,    outgoing list0)
// so every warp walks ONE contributor list at a time, fully coalesced.
__global__ __launch_bounds__(256, 7) void graph_kernel(
    const float* __restrict__ x,                  // [N_LG, D]
    const int* __restrict__ lg_node_idx,          // [N_LG, 2]
    const int* __restrict__ edge_index_labeled,   // [2, E_LAB]
    float* __restrict__ out)
{
    const int g = blockIdx.x;
    const int tid = threadIdx.x;
    const int wid = tid >> 5;
    const int lane = tid & 31;

    __shared__ int cur0[NPG], cur1[NPG];
    __shared__ int off0[NPG + 1], off1[NPG + 1];
    __shared__ int list0[LGPG], list1[LGPG];
    __shared__ int idx0[LGPG], idx1[LGPG];
    __shared__ float inv0[NPG], inv1[NPG];

    if (tid < NPG) { cur0[tid] = 0; cur1[tid] = 0; }
    __syncthreads();

    if (tid < LGPG) {
        int2 p = reinterpret_cast<const int2*>(lg_node_idx)[g * LGPG + tid];
        idx0[tid] = p.x; idx1[tid] = p.y;
        atomicAdd(&cur0[p.x], 1);
        atomicAdd(&cur1[p.y], 1);
    }
    __syncthreads();

    if (tid == 0) {
        int s = 0;
        #pragma unroll
        for (int n = 0; n < NPG; n++) { off0[n] = s; s += cur0[n]; }
        off0[NPG] = s;
    } else if (tid == 32) {
        int s = 0;
        #pragma unroll
        for (int n = 0; n < NPG; n++) { off1[n] = s; s += cur1[n]; }
        off1[NPG] = s;
    }
    __syncthreads();

    if (tid < NPG) {
        int c0 = off0[tid + 1] - off0[tid];
        int c1 = off1[tid + 1] - off1[tid];
        inv0[tid] = c0 > 0 ? 1.0f / (float)c0 : 0.0f;
        inv1[tid] = c1 > 0 ? 1.0f / (float)c1 : 0.0f;
        cur0[tid] = off0[tid];
        cur1[tid] = off1[tid];
    }
    __syncthreads();

    if (tid < LGPG) {
        list0[atomicAdd(&cur0[idx0[tid]], 1)] = tid;
        list1[atomicAdd(&cur1[idx1[tid]], 1)] = tid;
    }
    __syncthreads();

    const float4* xv = reinterpret_cast<const float4*>(x) + (size_t)g * (LGPG * ROWV);
    float4* ov = reinterpret_cast<float4*>(out) + (size_t)g * (NPG * ROWV);

    for (int n = wid; n < NPG; n += 8) {
        const int s1 = off1[n], e1 = off1[n + 1];
        const int s0 = off0[n], e0 = off0[n + 1];
        const float v1 = inv1[n], v0 = inv0[n];
        float4* onv = ov + n * ROWV;

        // seg A: incoming, dq = lane (all 32 lanes)
        {
            float4 a = make_float4(0.f, 0.f, 0.f, 0.f);
            for (int k = s1; k < e1; k++) {
                float4 t = ldcs4(&xv[list1[k] * ROWV + lane]);
                a.x += t.x; a.y += t.y; a.z += t.z; a.w += t.w;
            }
            a.x *= v1; a.y *= v1; a.z *= v1; a.w *= v1;
            stcs4(&onv[lane], a);
        }
        // seg B: incoming, dq = 32 + lane (lanes < 18)
        if (lane < 18) {
            int dq = 32 + lane;
            float4 a = make_float4(0.f, 0.f, 0.f, 0.f);
            for (int k = s1; k < e1; k++) {
                float4 t = ldcs4(&xv[list1[k] * ROWV + dq]);
                a.x += t.x; a.y += t.y; a.z += t.z; a.w += t.w;
            }
            a.x *= v1; a.y *= v1; a.z *= v1; a.w *= v1;
            stcs4(&onv[dq], a);
        }
        // seg C: outgoing, dq = 50 + lane (lanes < 25)
        if (lane < 25) {
            int dq = 50 + lane;
            float4 a = make_float4(0.f, 0.f, 0.f, 0.f);
            for (int k = s0; k < e0; k++) {
                float4 t = ldcs4(&xv[list0[k] * ROWV + dq]);
                a.x += t.x; a.y += t.y; a.z += t.z; a.w += t.w;
            }
            a.x *= v0; a.y *= v0; a.z *= v0; a.w *= v0;
            stcs4(&onv[dq], a);
        }
    }

    // Aux outputs (fused)
    if (tid < 2 * ELPG) {
        int r = tid / ELPG, e = tid % ELPG;
        int gi = r * E_LAB + g * ELPG + e;
        out[OFF_EDGE + gi] = (float)(edge_index_labeled[gi] - g * LGPG);
    } else if (tid >= 64 && tid < 64 + NPG) {
        out[OFF_BATCH + g * NPG + (tid - 64)] = (float)g;
    } else if (tid == 96) {
        out[OFF_PTR + g] = (float)(g * NPG);
        if (g == B_GRAPHS - 1) out[OFF_PTR + B_GRAPHS] = (float)(B_GRAPHS * NPG);
    }
}

extern "C" void kernel_launch(void* const* d_in, const int* in_sizes, int n_in,
                              void* d_out, int out_size) {
    const float* x            = (const float*)d_in[0];
    const int*   lg_node_idx  = (const int*)d_in[1];
    const int*   edge_idx_lab = (const int*)d_in[5];
    float* out = (float*)d_out;

    graph_kernel<<<B_GRAPHS, 256>>>(x, lg_node_idx, edge_idx_lab, out);
}

// round 4
// speedup vs baseline: 2.2688x; 1.0321x over previous
#include <cuda_runtime.h>
#include <cuda_bf16.h>

// Problem constants (fixed by setup_inputs)
#define B_GRAPHS 2000
#define LGPG 100      // line-graph nodes per graph
#define NPG 20        // original nodes per graph
#define ELPG 10       // labeled edges per graph
#define D 300
#define ROWV 75       // float4 per row (300/4)
#define N_LG (B_GRAPHS * LGPG)
#define N_NODES (B_GRAPHS * NPG)
#define E_LAB (B_GRAPHS * ELPG)

// Output layout (flattened tuple, float32):
//  [0, 12,000,000)              x_new  [N_NODES, D]
//  [12,000,000, 12,040,000)     edge_index_labeled_new [2, E_LAB]
//  [12,040,000, 12,042,001)     ptr_new [B+1]
//  [12,042,001, 12,082,001)     batch_vec [N_NODES]
#define OFF_EDGE 12000000
#define OFF_PTR  12040000
#define OFF_BATCH 12042001

__device__ __forceinline__ float4 ldcs4(const float4* p) {
    float4 v;
    asm volatile("ld.global.cs.v4.f32 {%0,%1,%2,%3}, [%4];"
                 : "=f"(v.x), "=f"(v.y), "=f"(v.z), "=f"(v.w) : "l"(p));
    return v;
}
__device__ __forceinline__ void stcs4(float4* p, float4 v) {
    asm volatile("st.global.cs.v4.f32 [%0], {%1,%2,%3,%4};"
                 :: "l"(p), "f"(v.x), "f"(v.y), "f"(v.z), "f"(v.w) : "memory");
}

// One CTA per graph. Build per-node CSR contributor lists for both keys,
// then GATHER with high MLP:
//   incoming half (cols 0..49 in float4): one loop, 2 independent LDGs/iter
//     (dq=lane for all lanes, dq=lane+32 predicated lane<18)
//   outgoing half (cols 50..74): unroll-by-2 with dual accumulators
__global__ __launch_bounds__(256, 7) void graph_kernel(
    const float* __restrict__ x,                  // [N_LG, D]
    const int* __restrict__ lg_node_idx,          // [N_LG, 2]
    const int* __restrict__ edge_index_labeled,   // [2, E_LAB]
    float* __restrict__ out)
{
    const int g = blockIdx.x;
    const int tid = threadIdx.x;
    const int wid = tid >> 5;
    const int lane = tid & 31;

    __shared__ int cur0[NPG], cur1[NPG];
    __shared__ int off0[NPG + 1], off1[NPG + 1];
    __shared__ int list0[LGPG], list1[LGPG];
    __shared__ int idx0[LGPG], idx1[LGPG];
    __shared__ float inv0[NPG], inv1[NPG];

    if (tid < NPG) { cur0[tid] = 0; cur1[tid] = 0; }
    __syncthreads();

    if (tid < LGPG) {
        int2 p = reinterpret_cast<const int2*>(lg_node_idx)[g * LGPG + tid];
        idx0[tid] = p.x; idx1[tid] = p.y;
        atomicAdd(&cur0[p.x], 1);
        atomicAdd(&cur1[p.y], 1);
    }
    __syncthreads();

    if (tid == 0) {
        int s = 0;
        #pragma unroll
        for (int n = 0; n < NPG; n++) { off0[n] = s; s += cur0[n]; }
        off0[NPG] = s;
    } else if (tid == 32) {
        int s = 0;
        #pragma unroll
        for (int n = 0; n < NPG; n++) { off1[n] = s; s += cur1[n]; }
        off1[NPG] = s;
    }
    __syncthreads();

    if (tid < NPG) {
        int c0 = off0[tid + 1] - off0[tid];
        int c1 = off1[tid + 1] - off1[tid];
        inv0[tid] = c0 > 0 ? 1.0f / (float)c0 : 0.0f;
        inv1[tid] = c1 > 0 ? 1.0f / (float)c1 : 0.0f;
        cur0[tid] = off0[tid];
        cur1[tid] = off1[tid];
    }
    __syncthreads();

    if (tid < LGPG) {
        list0[atomicAdd(&cur0[idx0[tid]], 1)] = tid;
        list1[atomicAdd(&cur1[idx1[tid]], 1)] = tid;
    }
    __syncthreads();

    const float4* xv = reinterpret_cast<const float4*>(x) + (size_t)g * (LGPG * ROWV);
    float4* ov = reinterpret_cast<float4*>(out) + (size_t)g * (NPG * ROWV);

    for (int n = wid; n < NPG; n += 8) {
        const int s1 = off1[n], e1 = off1[n + 1];
        const int s0 = off0[n], e0 = off0[n + 1];
        const float v1 = inv1[n], v0 = inv0[n];
        float4* onv = ov + n * ROWV;
        const bool hasB = (lane < 18);

        // incoming half: fused segments, 2 LDGs per iteration
        {
            float4 a0 = make_float4(0.f, 0.f, 0.f, 0.f);
            float4 a1 = make_float4(0.f, 0.f, 0.f, 0.f);
            for (int k = s1; k < e1; k++) {
                const float4* row = xv + list1[k] * ROWV;
                float4 t0 = ldcs4(row + lane);
                float4 t1;
                if (hasB) t1 = ldcs4(row + lane + 32);
                a0.x += t0.x; a0.y += t0.y; a0.z += t0.z; a0.w += t0.w;
                if (hasB) { a1.x += t1.x; a1.y += t1.y; a1.z += t1.z; a1.w += t1.w; }
            }
            a0.x *= v1; a0.y *= v1; a0.z *= v1; a0.w *= v1;
            stcs4(&onv[lane], a0);
            if (hasB) {
                a1.x *= v1; a1.y *= v1; a1.z *= v1; a1.w *= v1;
                stcs4(&onv[lane + 32], a1);
            }
        }

        // outgoing half: unroll-by-2, dual accumulators
        if (lane < 25) {
            const int dq = 50 + lane;
            float4 a0 = make_float4(0.f, 0.f, 0.f, 0.f);
            float4 a1 = make_float4(0.f, 0.f, 0.f, 0.f);
            int k = s0;
            for (; k + 1 < e0; k += 2) {
                float4 t0 = ldcs4(xv + list0[k] * ROWV + dq);
                float4 t1 = ldcs4(xv + list0[k + 1] * ROWV + dq);
                a0.x += t0.x; a0.y += t0.y; a0.z += t0.z; a0.w += t0.w;
                a1.x += t1.x; a1.y += t1.y; a1.z += t1.z; a1.w += t1.w;
            }
            if (k < e0) {
                float4 t0 = ldcs4(xv + list0[k] * ROWV + dq);
                a0.x += t0.x; a0.y += t0.y; a0.z += t0.z; a0.w += t0.w;
            }
            float4 r;
            r.x = (a0.x + a1.x) * v0;
            r.y = (a0.y + a1.y) * v0;
            r.z = (a0.z + a1.z) * v0;
            r.w = (a0.w + a1.w) * v0;
            stcs4(&onv[dq], r);
        }
    }

    // Aux outputs (fused)
    if (tid < 2 * ELPG) {
        int r = tid / ELPG, e = tid % ELPG;
        int gi = r * E_LAB + g * ELPG + e;
        out[OFF_EDGE + gi] = (float)(edge_index_labeled[gi] - g * LGPG);
    } else if (tid >= 64 && tid < 64 + NPG) {
        out[OFF_BATCH + g * NPG + (tid - 64)] = (float)g;
    } else if (tid == 96) {
        out[OFF_PTR + g] = (float)(g * NPG);
        if (g == B_GRAPHS - 1) out[OFF_PTR + B_GRAPHS] = (float)(B_GRAPHS * NPG);
    }
}

extern "C" void kernel_launch(void* const* d_in, const int* in_sizes, int n_in,
                              void* d_out, int out_size) {
    const float* x            = (const float*)d_in[0];
    const int*   lg_node_idx  = (const int*)d_in[1];
    const int*   edge_idx_lab = (const int*)d_in[5];
    float* out = (float*)d_out;

    graph_kernel<<<B_GRAPHS, 256>>>(x, lg_node_idx, edge_idx_lab, out);
}